// round 5
// baseline (speedup 1.0000x reference)
#include <cuda_runtime.h>
#include <cuda_fp16.h>

// Problem constants
#define N_NODE 50000
#define N_EDGE 500000
#define RATES  2
#define VOCAB  4096
#define MS     128
#define OUTU   256
#define BAS    4

// ---------------- scratch (device globals; no allocation allowed) ----------
__device__ __align__(16) float  g_W[RATES * VOCAB * MS];             // 4 MB fp32
__device__ __align__(16) __half g_Mh[RATES * 3 * VOCAB * OUTU];      // 12.5 MB fp16
__device__ __align__(16) __half g_ph[2 * RATES * N_NODE * OUTU];     // 102 MB fp16
__device__ int g_cnt[2][N_NODE + 1];
__device__ int g_off[2][N_NODE + 1];
__device__ int g_cur[2][N_NODE];
__device__ int g_sorted[2][RATES * N_EDGE];                          // 8 MB

// ---------------- kernel 1: W[r] = att[r] @ basis ---------------------------
__global__ void __launch_bounds__(256) k_W(const float* __restrict__ att,
                                           const float* __restrict__ basis) {
    int idx = blockIdx.x * blockDim.x + threadIdx.x;
    if (idx >= RATES * VOCAB * MS) return;
    int r  = idx / (VOCAB * MS);
    int im = idx % (VOCAB * MS);
    float s = 0.f;
#pragma unroll
    for (int b = 0; b < BAS; b++)
        s += __ldg(&att[r * BAS + b]) * __ldg(&basis[b * (VOCAB * MS) + im]);
    g_W[idx] = s;
}

// ---------------- kernel 2: M[r][k] = W[r] @ fc_w[:,128k:+128]^T (fp16 out) -
__global__ void __launch_bounds__(256) k_M(const float* __restrict__ fc_w) {
    int rk = blockIdx.z;
    int r = rk / 3, k = rk % 3;
    int i0 = blockIdx.x * 64;
    int o0 = blockIdx.y * 64;
    __shared__ float As[32][65];
    __shared__ float Bs[32][65];
    int tid = threadIdx.x;
    int tx = tid & 15, ty = tid >> 4;
    float acc[4][4];
#pragma unroll
    for (int u = 0; u < 4; u++)
#pragma unroll
        for (int v = 0; v < 4; v++) acc[u][v] = 0.f;

    const float* Wp = g_W + r * VOCAB * MS;
    for (int mc = 0; mc < MS; mc += 32) {
#pragma unroll
        for (int j = 0; j < 8; j++) {
            int f = j * 256 + tid;
            int ii = f >> 5, mm = f & 31;
            As[mm][ii] = Wp[(i0 + ii) * MS + mc + mm];
            Bs[mm][ii] = fc_w[(o0 + ii) * (3 * MS) + k * MS + mc + mm];
        }
        __syncthreads();
#pragma unroll
        for (int mm = 0; mm < 32; mm++) {
            float a[4], b[4];
#pragma unroll
            for (int u = 0; u < 4; u++) { a[u] = As[mm][ty * 4 + u]; b[u] = Bs[mm][tx * 4 + u]; }
#pragma unroll
            for (int u = 0; u < 4; u++)
#pragma unroll
                for (int v = 0; v < 4; v++) acc[u][v] += a[u] * b[v];
        }
        __syncthreads();
    }
    __half* Mout = g_Mh + (size_t)((r * 3 + k) * VOCAB) * OUTU;
#pragma unroll
    for (int u = 0; u < 4; u++) {
        __half2 h0 = __floats2half2_rn(acc[u][0], acc[u][1]);
        __half2 h1 = __floats2half2_rn(acc[u][2], acc[u][3]);
        uint2 pk;
        pk.x = *(unsigned int*)&h0;
        pk.y = *(unsigned int*)&h1;
        *(uint2*)(&Mout[(size_t)(i0 + ty * 4 + u) * OUTU + o0 + tx * 4]) = pk;
    }
}

// ---------------- kernel 3: p[side][r][n] = cj[n]*sum_k M[r][k][feat[n,k]] --
// ONE SIDE per launch; one warp per (r, node); lane owns one uint4 (8 halves)
__global__ void __launch_bounds__(256) k_p(int side,
                                           const int* __restrict__ feat,
                                           const float* __restrict__ cj) {
    int gw = (blockIdx.x * blockDim.x + threadIdx.x) >> 5;
    int lane = threadIdx.x & 31;
    if (gw >= RATES * N_NODE) return;
    int r = gw / N_NODE, n = gw % N_NODE;

    float cjv = __ldg(&cj[n]);
    int f0 = __ldg(&feat[n * 3 + 0]);
    int f1 = __ldg(&feat[n * 3 + 1]);
    int f2 = __ldg(&feat[n * 3 + 2]);

    const uint4* m0 = (const uint4*)(g_Mh + (size_t)((r * 3 + 0) * VOCAB + f0) * OUTU);
    const uint4* m1 = (const uint4*)(g_Mh + (size_t)((r * 3 + 1) * VOCAB + f1) * OUTU);
    const uint4* m2 = (const uint4*)(g_Mh + (size_t)((r * 3 + 2) * VOCAB + f2) * OUTU);
    uint4* out = (uint4*)(g_ph + (size_t)((side * RATES + r) * N_NODE + n) * OUTU);

    uint4 a = m0[lane], b = m1[lane], c = m2[lane];
    const unsigned int* au = (const unsigned int*)&a;
    const unsigned int* bu = (const unsigned int*)&b;
    const unsigned int* cu = (const unsigned int*)&c;
    uint4 o;
    unsigned int* ou = (unsigned int*)&o;
#pragma unroll
    for (int j = 0; j < 4; j++) {
        float2 fa = __half22float2(*(const __half2*)&au[j]);
        float2 fb = __half22float2(*(const __half2*)&bu[j]);
        float2 fc = __half22float2(*(const __half2*)&cu[j]);
        float2 s;
        s.x = cjv * (fa.x + fb.x + fc.x);
        s.y = cjv * (fa.y + fb.y + fc.y);
        __half2 h = __floats2half2_rn(s.x, s.y);
        ou[j] = *(unsigned int*)&h;
    }
    out[lane] = o;
}

// ---------------- kernel 4: zero histograms --------------------------------
__global__ void __launch_bounds__(256) k_zero() {
    int i = blockIdx.x * blockDim.x + threadIdx.x;
    if (i < 2 * (N_NODE + 1)) ((int*)g_cnt)[i] = 0;
}

// ---------------- kernel 5: per-destination edge histogram -----------------
__global__ void __launch_bounds__(256) k_count(const int* __restrict__ edge_src,
                                               const int* __restrict__ edge_dst) {
    for (int idx = blockIdx.x * blockDim.x + threadIdx.x; idx < RATES * N_EDGE;
         idx += gridDim.x * blockDim.x) {
        int s = __ldg(&edge_src[idx]);
        int d = __ldg(&edge_dst[idx]);
        atomicAdd(&g_cnt[0][s], 1);   // dir 0: drug_out CSR keyed by src
        atomicAdd(&g_cnt[1][d], 1);   // dir 1: dis_out  CSR keyed by dst
    }
}

// ---------------- kernel 6: exclusive scan -> offsets (one block per dir) ---
__global__ void __launch_bounds__(1024) k_scan() {
    const int T = 1024;
    int dir = blockIdx.x;
    int t = threadIdx.x;
    __shared__ int ssum[T];
    const int chunk = (N_NODE + T - 1) / T;
    int begin = t * chunk;
    int end = begin + chunk; if (end > N_NODE) end = N_NODE;
    int s = 0;
    for (int i = begin; i < end && begin < N_NODE; i++) s += g_cnt[dir][i];
    ssum[t] = s;
    __syncthreads();
    for (int ofs = 1; ofs < T; ofs <<= 1) {
        int v = (t >= ofs) ? ssum[t - ofs] : 0;
        __syncthreads();
        ssum[t] += v;
        __syncthreads();
    }
    int run = ssum[t] - s;
    for (int i = begin; i < end && begin < N_NODE; i++) {
        int c = g_cnt[dir][i];
        g_off[dir][i] = run;
        g_cur[dir][i] = run;
        run += c;
    }
    if (t == T - 1) g_off[dir][N_NODE] = ssum[T - 1];
}

// ---------------- kernel 7: scatter edge -> sorted gather index ------------
__global__ void __launch_bounds__(256) k_scatter(const int* __restrict__ edge_src,
                                                 const int* __restrict__ edge_dst) {
    for (int idx = blockIdx.x * blockDim.x + threadIdx.x; idx < RATES * N_EDGE;
         idx += gridDim.x * blockDim.x) {
        int r = idx / N_EDGE;
        int s = __ldg(&edge_src[idx]);
        int d = __ldg(&edge_dst[idx]);
        int p0 = atomicAdd(&g_cur[0][s], 1);
        g_sorted[0][p0] = r * N_NODE + d;   // drug_out pulls p_dis rows
        int p1 = atomicAdd(&g_cur[1][d], 1);
        g_sorted[1][p1] = r * N_NODE + s;   // dis_out pulls p_drug rows
    }
}

// ---------------- kernel 8: pull aggregation + scale + bias (one dir) ------
// one warp per node; lane owns 8 output cols; 4-deep MLP unroll
__global__ void __launch_bounds__(256) k_agg(int dir,
                                             const float* __restrict__ ci,
                                             const float* __restrict__ fc_b,
                                             float* __restrict__ out) {
    int node = blockIdx.x * 8 + (threadIdx.x >> 5);
    int lane = threadIdx.x & 31;
    if (node >= N_NODE) return;

    int start = g_off[dir][node];
    int end   = g_off[dir][node + 1];
    // dir 0 (drug_out) gathers p side 1 (dis); dir 1 (dis_out) gathers side 0
    const uint4* pbase = (const uint4*)(g_ph + (dir == 0 ? (size_t)RATES * N_NODE * OUTU : 0));
    const int* srt = g_sorted[dir];

    float acc[8];
#pragma unroll
    for (int j = 0; j < 8; j++) acc[j] = 0.f;

    int e = start;
    for (; e + 3 < end; e += 4) {
        int gi0 = __ldg(&srt[e]);
        int gi1 = __ldg(&srt[e + 1]);
        int gi2 = __ldg(&srt[e + 2]);
        int gi3 = __ldg(&srt[e + 3]);
        uint4 v0 = pbase[(size_t)gi0 * 32 + lane];
        uint4 v1 = pbase[(size_t)gi1 * 32 + lane];
        uint4 v2 = pbase[(size_t)gi2 * 32 + lane];
        uint4 v3 = pbase[(size_t)gi3 * 32 + lane];
        const unsigned int* u0 = (const unsigned int*)&v0;
        const unsigned int* u1 = (const unsigned int*)&v1;
        const unsigned int* u2 = (const unsigned int*)&v2;
        const unsigned int* u3 = (const unsigned int*)&v3;
#pragma unroll
        for (int j = 0; j < 4; j++) {
            float2 f0 = __half22float2(*(const __half2*)&u0[j]);
            float2 f1 = __half22float2(*(const __half2*)&u1[j]);
            float2 f2 = __half22float2(*(const __half2*)&u2[j]);
            float2 f3 = __half22float2(*(const __half2*)&u3[j]);
            acc[2 * j]     += (f0.x + f1.x) + (f2.x + f3.x);
            acc[2 * j + 1] += (f0.y + f1.y) + (f2.y + f3.y);
        }
    }
    for (; e < end; e++) {
        int gi = __ldg(&srt[e]);
        uint4 v = pbase[(size_t)gi * 32 + lane];
        const unsigned int* u = (const unsigned int*)&v;
#pragma unroll
        for (int j = 0; j < 4; j++) {
            float2 f = __half22float2(*(const __half2*)&u[j]);
            acc[2 * j]     += f.x;
            acc[2 * j + 1] += f.y;
        }
    }

    float civ = __ldg(&ci[node]);
    float4 b0 = ((const float4*)fc_b)[lane * 2];
    float4 b1 = ((const float4*)fc_b)[lane * 2 + 1];
    float4 o0, o1;
    o0.x = civ * acc[0] + b0.x;  o0.y = civ * acc[1] + b0.y;
    o0.z = civ * acc[2] + b0.z;  o0.w = civ * acc[3] + b0.w;
    o1.x = civ * acc[4] + b1.x;  o1.y = civ * acc[5] + b1.y;
    o1.z = civ * acc[6] + b1.z;  o1.w = civ * acc[7] + b1.w;
    size_t row = (dir == 0) ? (size_t)node : (size_t)(N_NODE + node);
    float4* orow = (float4*)out + row * (OUTU / 4);
    orow[lane * 2]     = o0;
    orow[lane * 2 + 1] = o1;
}

// ---------------- launch ---------------------------------------------------
extern "C" void kernel_launch(void* const* d_in, const int* in_sizes, int n_in,
                              void* d_out, int out_size) {
    const int*   drug_feat = (const int*)d_in[0];
    const int*   dis_feat  = (const int*)d_in[1];
    const int*   edge_src  = (const int*)d_in[2];
    const int*   edge_dst  = (const int*)d_in[3];
    const float* cj_drug   = (const float*)d_in[4];
    const float* ci_drug   = (const float*)d_in[5];
    const float* cj_dis    = (const float*)d_in[6];
    const float* ci_dis    = (const float*)d_in[7];
    const float* att       = (const float*)d_in[8];
    const float* basis     = (const float*)d_in[9];
    const float* fc_w      = (const float*)d_in[10];
    const float* fc_b      = (const float*)d_in[11];
    float* out = (float*)d_out;

    // Streams/events: created during the capture call only (replays run the
    // graph, no host code). No device allocation involved.
    static cudaStream_t s2 = 0, s3 = 0;
    static cudaEvent_t evFork = 0, evCSR = 0, evM = 0, evP0 = 0;
    static bool inited = false;
    bool forked = inited;
    if (!inited) {
        forked = (cudaStreamCreateWithFlags(&s2, cudaStreamNonBlocking) == cudaSuccess) &&
                 (cudaStreamCreateWithFlags(&s3, cudaStreamNonBlocking) == cudaSuccess) &&
                 (cudaEventCreateWithFlags(&evFork, cudaEventDisableTiming) == cudaSuccess) &&
                 (cudaEventCreateWithFlags(&evCSR, cudaEventDisableTiming) == cudaSuccess) &&
                 (cudaEventCreateWithFlags(&evM, cudaEventDisableTiming) == cudaSuccess) &&
                 (cudaEventCreateWithFlags(&evP0, cudaEventDisableTiming) == cudaSuccess);
        inited = forked;  // retry next call if creation failed
    }

    int pblocks = (RATES * N_NODE + 7) / 8;   // 8 warps per 256-thr block
    int ablocks = (N_NODE + 7) / 8;

    if (forked) {
        cudaEventRecord(evFork, 0);
        cudaStreamWaitEvent(s2, evFork, 0);
        cudaStreamWaitEvent(s3, evFork, 0);

        // --- CSR chain (stream s2) ---
        k_zero<<<(2 * (N_NODE + 1) + 255) / 256, 256, 0, s2>>>();
        k_count<<<1184, 256, 0, s2>>>(edge_src, edge_dst);
        k_scan<<<2, 1024, 0, s2>>>();
        k_scatter<<<1184, 256, 0, s2>>>(edge_src, edge_dst);
        cudaEventRecord(evCSR, s2);

        // --- message chain head (default stream) ---
        k_W<<<(RATES * VOCAB * MS + 255) / 256, 256>>>(att, basis);
        dim3 gM(VOCAB / 64, OUTU / 64, RATES * 3);
        k_M<<<gM, 256>>>(fc_w);
        cudaEventRecord(evM, 0);

        // --- p halves concurrently: side 1 (dis) on default, side 0 on s3 ---
        k_p<<<pblocks, 256>>>(1, dis_feat, cj_dis);
        cudaStreamWaitEvent(s3, evM, 0);
        k_p<<<pblocks, 256, 0, s3>>>(0, drug_feat, cj_drug);
        cudaEventRecord(evP0, s3);

        // --- agg 0 (needs p side 1 + CSR), then agg 1 (needs p side 0) ---
        cudaStreamWaitEvent(0, evCSR, 0);
        k_agg<<<ablocks, 256>>>(0, ci_drug, fc_b, out);
        cudaStreamWaitEvent(0, evP0, 0);
        k_agg<<<ablocks, 256>>>(1, ci_dis, fc_b, out);
    } else {
        // Fallback: single-stream version (correct, slower)
        k_zero<<<(2 * (N_NODE + 1) + 255) / 256, 256>>>();
        k_count<<<1184, 256>>>(edge_src, edge_dst);
        k_scan<<<2, 1024>>>();
        k_scatter<<<1184, 256>>>(edge_src, edge_dst);
        k_W<<<(RATES * VOCAB * MS + 255) / 256, 256>>>(att, basis);
        dim3 gM(VOCAB / 64, OUTU / 64, RATES * 3);
        k_M<<<gM, 256>>>(fc_w);
        k_p<<<pblocks, 256>>>(1, dis_feat, cj_dis);
        k_p<<<pblocks, 256>>>(0, drug_feat, cj_drug);
        k_agg<<<ablocks, 256>>>(0, ci_drug, fc_b, out);
        k_agg<<<ablocks, 256>>>(1, ci_dis, fc_b, out);
    }
}